// round 13
// baseline (speedup 1.0000x reference)
#include <cuda_runtime.h>
#include <cstdint>

// ============================================================================
// NAS LSTM controller, 32 sequential steps, single persistent kernel.
// 64 worker CTAs x 512 threads (148 launched; extras exit). Weights in SMEM.
// 3 comm rounds/step, all slim: 8 published words per CTA per round (h slices
// or <=33 logit partials). Consumes are 1-poll-per-thread batched sweeps on
// epoch-tagged u64 words (tag<<32|float, relaxed gpu scope).
// hw2s and op logits computed locally/replicated (fixed order -> identical
// bits in every CTA). Exact JAX threefry2x32 sampling, all gumbels precomputed.
// ============================================================================

#define GRID   64
#define GRIDL  148
#define NT     512
#define D      512
#define LP1    33
#define NSTEP  32
#define OPSN   16

typedef unsigned long long u64t;

// ------------------------------ global state -------------------------------
__device__ u64t gPubH1[GRID * 8];    // [dim] h1 slices
__device__ u64t gPubH2[GRID * 8];    // [dim] h2 slices
__device__ u64t gPubI[GRID * 8];     // init h0 slices
__device__ u64t gPubL[LP1 * GRID];   // [anchor][src] node-logit partials
__device__ unsigned gEpochBase;

// ------------------------------ shared layout ------------------------------
struct __align__(16) SM {
    float Whh[32 * 512];       // 64 KB  own 32 gate rows of w_hh
    float Wih[32 * 512];       // 64 KB  own 32 gate rows of w_ih
    float A1[8 * 512];         // own rows of w_attn_1
    float A2R[8 * 512];        // own rows of w_attn_2
    float OPF[OPSN * 512];     // 32 KB  full op_fc
    float hprev[512];
    float h1full[512];
    float lsum[LP1 * 64];
    float embG[17 * 32];
    float anchG[LP1 * 32];
    float anchW1[LP1 * 8];
    float gnode[NSTEP * LP1];
    float gop[NSTEP * OPSN];
    float vals[40];
    float hw2s[8];
    float idxfc8[8];
    float bias[32];
    float gbuf[32];
    float cslice[8];
    float h1own[8];
    float h2own[8];
    float oplog[16];
    unsigned keys2[NSTEP * 2];
    int nodeIdx, opIdx, sel;
    float nodeLp, nodeEnt, opLp, opEnt, lpSum, entSum;
    unsigned base;
};

// --------------------------- tagged publish/poll ---------------------------
__device__ __forceinline__ void pub64(u64t* p, float v, unsigned tag) {
    u64t w = ((u64t)tag << 32) | (u64t)__float_as_uint(v);
    asm volatile("st.relaxed.gpu.global.u64 [%0], %1;" :: "l"(p), "l"(w) : "memory");
}
__device__ __forceinline__ u64t ldrx(const u64t* p) {
    u64t w;
    asm volatile("ld.relaxed.gpu.global.u64 %0, [%1];" : "=l"(w) : "l"(p) : "memory");
    return w;
}
__device__ __forceinline__ float lo32(u64t w) { return __uint_as_float((unsigned)w); }
__device__ __forceinline__ float poll1(const u64t* p, unsigned tag) {
    u64t w;
    do { w = ldrx(p); } while ((unsigned)(w >> 32) != tag);
    return lo32(w);
}

// ------------------------------ threefry2x32 -------------------------------
__device__ __forceinline__ void tf2x32(unsigned k0, unsigned k1,
                                       unsigned x0, unsigned x1,
                                       unsigned& o0, unsigned& o1) {
    unsigned ks2 = k0 ^ k1 ^ 0x1BD11BDAu;
    x0 += k0; x1 += k1;
#define TFR(r) { x0 += x1; x1 = (x1 << (r)) | (x1 >> (32 - (r))); x1 ^= x0; }
    TFR(13) TFR(15) TFR(26) TFR(6)   x0 += k1;  x1 += ks2 + 1u;
    TFR(17) TFR(29) TFR(16) TFR(24)  x0 += ks2; x1 += k0 + 2u;
    TFR(13) TFR(15) TFR(26) TFR(6)   x0 += k0;  x1 += k1 + 3u;
    TFR(17) TFR(29) TFR(16) TFR(24)  x0 += k1;  x1 += ks2 + 4u;
    TFR(13) TFR(15) TFR(26) TFR(6)   x0 += ks2; x1 += k0 + 5u;
#undef TFR
    o0 = x0; o1 = x1;
}

__device__ __forceinline__ float gumbelf(unsigned bits) {
    float f = __uint_as_float((bits >> 9) | 0x3f800000u) - 1.0f;
    const float tiny = 1.17549435e-38f;
    float u = fmaxf(tiny, f * (1.0f - tiny) + tiny);
    return -logf(-logf(u));
}

__device__ __forceinline__ float sigf(float x) {
    return __fdividef(1.0f, 1.0f + __expf(-x));
}
__device__ __forceinline__ float tanhfast(float x) {
    return 1.0f - __fdividef(2.0f, __expf(2.0f * x) + 1.0f);
}

// LSTM cell: gates = Whh*hin + xc; update own c,h; tid<8 publishes h slice
// immediately (no trailing block sync -- caller's barriers cover hazards).
__device__ __forceinline__ void cell_hh(SM* s, const float* hin, const float* xc,
                                        int tid, float* houtOwn,
                                        u64t* pubBase, unsigned tag) {
    int row = tid >> 4, lane = tid & 15;
    const float4* wp = (const float4*)&s->Whh[row * 512];
    const float4* vp = (const float4*)hin;
    float acc = 0.f;
#pragma unroll
    for (int i = 0; i < 8; i++) {
        float4 w = wp[i * 16 + lane], v = vp[i * 16 + lane];
        acc += w.x * v.x + w.y * v.y + w.z * v.z + w.w * v.w;
    }
#pragma unroll
    for (int o = 8; o; o >>= 1) acc += __shfl_down_sync(0xffffffffu, acc, o, 16);
    if (lane == 0) s->gbuf[row] = acc + xc[row];
    __syncthreads();
    if (tid < 8) {
        float gi = s->gbuf[tid],      gf = s->gbuf[8 + tid];
        float gg = s->gbuf[16 + tid], go = s->gbuf[24 + tid];
        float c2 = sigf(gf) * s->cslice[tid] + sigf(gi) * tanhfast(gg);
        float h2 = sigf(go) * tanhfast(c2);
        s->cslice[tid] = c2;
        houtOwn[tid] = h2;
        pub64(pubBase + tid, h2, tag);
    }
}

// 8 dots of an 8x512 smem matrix with v (threads 0..127), conflict-free.
__device__ __forceinline__ void attn_dot(const float* M, const float* v,
                                         float* dst, int tid) {
    if (tid < 128) {
        int r = tid >> 4, lane = tid & 15;
        const float4* mp = (const float4*)&M[r * 512];
        const float4* vp = (const float4*)v;
        float acc = 0.f;
#pragma unroll
        for (int i = 0; i < 8; i++) {
            float4 w = mp[i * 16 + lane], x = vp[i * 16 + lane];
            acc += w.x * x.x + w.y * x.y + w.z * x.z + w.w * x.w;
        }
#pragma unroll
        for (int o = 8; o; o >>= 1) acc += __shfl_down_sync(0xffffffffu, acc, o, 16);
        if (lane == 0) dst[r] = acc;
    }
}

// ----- warp-parallel categorical sample + lp + entropy (tid<32 only) -------
__device__ __forceinline__ void warp_sample(const float* vals, const float* g, int n,
                                            int* oIdx, float* oLp, float* oEnt, int lane) {
    const float NINF = __int_as_float(0xff800000);
    float v1 = (lane < n) ? vals[lane] : NINF;
    float d1 = (lane < n) ? v1 + g[lane] : NINF;
    int   i1 = lane;
    float v2 = NINF;
    if (lane == 0 && n > 32) {
        v2 = vals[32];
        float d2 = v2 + g[32];
        if (d2 > d1) { d1 = d2; i1 = 32; }
    }
#pragma unroll
    for (int off = 16; off; off >>= 1) {
        float dv = __shfl_down_sync(0xffffffffu, d1, off);
        int   di = __shfl_down_sync(0xffffffffu, i1, off);
        if (dv > d1 || (dv == d1 && di < i1)) { d1 = dv; i1 = di; }
    }
    int best = __shfl_sync(0xffffffffu, i1, 0);
    float m1 = (lane < n) ? v1 : NINF;
    if (lane == 0 && n > 32) m1 = fmaxf(m1, v2);
#pragma unroll
    for (int off = 16; off; off >>= 1) m1 = fmaxf(m1, __shfl_xor_sync(0xffffffffu, m1, off));
    float se = (lane < n) ? __expf(v1 - m1) : 0.f;
    if (lane == 0 && n > 32) se += __expf(v2 - m1);
#pragma unroll
    for (int off = 16; off; off >>= 1) se += __shfl_xor_sync(0xffffffffu, se, off);
    float lse = __logf(se);
    float ent = 0.f;
    if (lane < n)            { float l = v1 - m1 - lse; ent -= l * __expf(l); }
    if (lane == 0 && n > 32) { float l = v2 - m1 - lse; ent -= l * __expf(l); }
#pragma unroll
    for (int off = 16; off; off >>= 1) ent += __shfl_xor_sync(0xffffffffu, ent, off);
    if (lane == 0) {
        *oIdx = best;
        *oLp  = -(vals[best] - m1 - lse);
        *oEnt = ent;
    }
}

__global__ void __launch_bounds__(NT, 1)
controller_kernel(const float* __restrict__ emb,   const float* __restrict__ w_ih,
                  const float* __restrict__ w_hh,  const float* __restrict__ b_ih,
                  const float* __restrict__ b_hh,  const float* __restrict__ w1,
                  const float* __restrict__ w2,    const float* __restrict__ idxfc,
                  const float* __restrict__ opfc,  float* __restrict__ out) {
    if (blockIdx.x >= GRID) return;
    extern __shared__ __align__(16) float smraw[];
    SM* s = (SM*)smraw;
    const int tid = threadIdx.x;
    const int b   = blockIdx.x;

    // ---------------- setup ----------------
    if (tid == 0) {
        s->base = *(volatile unsigned*)&gEpochBase;
        s->sel = OPSN;
        s->lpSum = 0.f; s->entSum = 0.f;
    }
    for (int i = tid; i < 32 * 512; i += NT) {
        int row = i >> 9, k = i & 511;
        int gate = row >> 3, jj = row & 7;
        int grow = gate * 512 + b * 8 + jj;
        s->Whh[i] = w_hh[grow * 512 + k];
        s->Wih[i] = w_ih[grow * 512 + k];
    }
    for (int i = tid; i < 8 * 512; i += NT) {
        int a = i >> 9, k = i & 511;
        s->A1[i]  = w1[(b * 8 + a) * 512 + k];
        s->A2R[i] = w2[(b * 8 + a) * 512 + k];
    }
    for (int i = tid; i < OPSN * 512; i += NT) s->OPF[i] = opfc[i];
    if (tid < 32) {
        int gate = tid >> 3, jj = tid & 7;
        int grow = gate * 512 + b * 8 + jj;
        float bb = b_ih[grow] + b_hh[grow];
        s->bias[tid]  = bb;
        s->anchG[tid] = bb;      // anchor 0 = zeros -> x-gates = bias
    }
    if (tid < 8) { s->idxfc8[tid] = idxfc[b * 8 + tid]; s->cslice[tid] = 0.f; }
    if (tid < LP1 * 8) s->anchW1[tid] = 0.f;
    __syncthreads();

    // embGates for all 17 embeddings
    {
        int row = tid >> 4, lane = tid & 15;
        const float4* wr = (const float4*)&s->Wih[row * 512];
        for (int e = 0; e < 17; e++) {
            const float4* er = (const float4*)&emb[e * 512];
            float acc = 0.f;
#pragma unroll
            for (int i = 0; i < 8; i++) {
                float4 w = wr[i * 16 + lane];
                float4 v = __ldg(&er[i * 16 + lane]);
                acc += w.x * v.x + w.y * v.y + w.z * v.z + w.w * v.w;
            }
#pragma unroll
            for (int o = 8; o; o >>= 1) acc += __shfl_down_sync(0xffffffffu, acc, o, 16);
            if (lane == 0) s->embG[e * 32 + row] = acc + s->bias[row];
        }
    }
    // key chain (data-independent)
    if (tid == 0) {
        unsigned k0 = 0u, k1 = 42u;
        for (int t = 0; t < NSTEP; t++) {
            s->keys2[2 * t] = k0; s->keys2[2 * t + 1] = k1;
            unsigned o0, o1; tf2x32(k0, k1, 0u, 2u, o0, o1);
            k0 = o0; k1 = o1;
        }
    }
    __syncthreads();
    for (int p = tid; p < NSTEP * (LP1 + OPSN); p += NT) {
        int t = p / (LP1 + OPSN), r = p % (LP1 + OPSN);
        unsigned K0 = s->keys2[2 * t], K1 = s->keys2[2 * t + 1];
        unsigned c0, c1, o0, o1;
        if (r < LP1) {
            tf2x32(K0, K1, 0u, 0u, c0, c1);
            tf2x32(c0, c1, 0u, (unsigned)r, o0, o1);
            s->gnode[t * LP1 + r] = gumbelf(o0 ^ o1);
        } else {
            int o = r - LP1;
            tf2x32(K0, K1, 0u, 1u, c0, c1);
            tf2x32(c0, c1, 0u, (unsigned)o, o0, o1);
            s->gop[t * OPSN + o] = gumbelf(o0 ^ o1);
        }
    }
    __syncthreads();
    const unsigned base = s->base;

    // ---------------- initial cell: h0 = cell(emb[16], 0, 0) ----------------
    if (tid < 8) {
        float gi = s->embG[16 * 32 + tid];
        float gg = s->embG[16 * 32 + 16 + tid], go = s->embG[16 * 32 + 24 + tid];
        float c2 = sigf(gi) * tanhfast(gg);
        float h2 = sigf(go) * tanhfast(c2);
        s->cslice[tid] = c2;
        pub64(&gPubI[b * 8 + tid], h2, base + 1);
    }
    s->hprev[tid] = poll1(&gPubI[tid], base + 1);
    __syncthreads();
    if (b == 0 && tid == 0) *(volatile unsigned*)&gEpochBase = base + 128;

    // ---------------- main loop ----------------
    for (int t = 0; t < NSTEP; t++) {
        const unsigned tag1 = base + 2 + 3 * t;
        const unsigned tag2 = tag1 + 1;
        const unsigned tag3 = tag1 + 2;

        // cell1: h1 = cell(emb[sel], hprev, c); tid<8 publishes h1 slice
        cell_hh(s, s->hprev, &s->embG[s->sel * 32], tid, s->h1own,
                &gPubH1[b * 8], tag1);

        // overlap comm latency: anchor-t x-gates + anchW1[t] from hprev
        if (t > 0) {
            int row = tid >> 4, lane = tid & 15;
            const float4* wp = (const float4*)&s->Wih[row * 512];
            const float4* vp = (const float4*)s->hprev;
            float acc = 0.f;
#pragma unroll
            for (int i = 0; i < 8; i++) {
                float4 w = wp[i * 16 + lane], v = vp[i * 16 + lane];
                acc += w.x * v.x + w.y * v.y + w.z * v.z + w.w * v.w;
            }
#pragma unroll
            for (int o = 8; o; o >>= 1) acc += __shfl_down_sync(0xffffffffu, acc, o, 16);
            if (lane == 0) s->anchG[t * 32 + row] = acc + s->bias[row];
        }
        attn_dot(s->A1, s->hprev, &s->anchW1[t * 8], tid);

        // consume round1: 1 poll/thread -> full h1
        s->h1full[tid] = poll1(&gPubH1[tid], tag1);
        __syncthreads();   // (B)

        // hw2s for own 8 dims, locally from A2 rows x h1full
        attn_dot(s->A2R, s->h1full, s->hw2s, tid);
        __syncthreads();   // (C)

        // node-logit partial for own 8 dims, anchors 0..t; publish
        if (tid < 288) {
            int a = tid >> 3; if (a > 32) a = 32;
            int rl = tid & 7;
            float q = tanhfast(s->anchW1[a * 8 + rl] + s->hw2s[rl]) * s->idxfc8[rl];
#pragma unroll
            for (int o = 4; o; o >>= 1) q += __shfl_down_sync(0xffffffffu, q, o, 8);
            if (rl == 0 && tid < 264 && a <= t) pub64(&gPubL[a * 64 + b], q, tag2);
        }

        // consume round2: (t+1)*64 words, batched <=4 polls/thread
        {
            int cnt = (t + 1) * 64;
            int k0 = tid, k1 = tid + 512, k2 = tid + 1024, k3 = tid + 1536;
            unsigned need = (k0 < cnt ? 1u : 0u) | (k1 < cnt ? 2u : 0u) |
                            (k2 < cnt ? 4u : 0u) | (k3 < cnt ? 8u : 0u);
            unsigned got = 0;
            float v0 = 0.f, v1 = 0.f, v2 = 0.f, v3 = 0.f;
            while (got != need) {
                u64t w;
                if ((need & 1u) && !(got & 1u)) { w = ldrx(&gPubL[k0]); if ((unsigned)(w >> 32) == tag2) { v0 = lo32(w); got |= 1u; } }
                if ((need & 2u) && !(got & 2u)) { w = ldrx(&gPubL[k1]); if ((unsigned)(w >> 32) == tag2) { v1 = lo32(w); got |= 2u; } }
                if ((need & 4u) && !(got & 4u)) { w = ldrx(&gPubL[k2]); if ((unsigned)(w >> 32) == tag2) { v2 = lo32(w); got |= 4u; } }
                if ((need & 8u) && !(got & 8u)) { w = ldrx(&gPubL[k3]); if ((unsigned)(w >> 32) == tag2) { v3 = lo32(w); got |= 8u; } }
            }
            if (need & 1u) s->lsum[k0] = v0;
            if (need & 2u) s->lsum[k1] = v1;
            if (need & 4u) s->lsum[k2] = v2;
            if (need & 8u) s->lsum[k3] = v3;
        }
        __syncthreads();   // (D)
        if (tid < LP1) {
            float v;
            if (tid <= t) {
                const float4* lp = (const float4*)&s->lsum[tid * 64];
                v = 0.f;
#pragma unroll
                for (int i = 0; i < 16; i++) { float4 x = lp[i]; v += x.x + x.y + x.z + x.w; }
                v = 2.5f * tanhfast(v * 0.2f);
            } else v = -1e9f;
            s->vals[tid] = v;
        }
        __syncthreads();   // (E)
        if (tid < 32)
            warp_sample(s->vals, &s->gnode[t * LP1], LP1,
                        &s->nodeIdx, &s->nodeLp, &s->nodeEnt, tid);
        __syncthreads();   // (F)

        // cell2: h2 = cell(anchor[nodeIdx], h1, c); tid<8 publishes h2 slice
        cell_hh(s, s->h1full, &s->anchG[s->nodeIdx * 32], tid, s->h2own,
                &gPubH2[b * 8], tag3);

        // consume round3: 1 poll/thread -> full h2 into hprev
        s->hprev[tid] = poll1(&gPubH2[tid], tag3);
        __syncthreads();   // (G)

        // op logits replicated: 16 warps, one op each (fixed order, identical
        // bits in every CTA)
        {
            int w = tid >> 5, lane = tid & 31;
            const float4* mp = (const float4*)&s->OPF[w * 512];
            const float4* vp = (const float4*)s->hprev;
            float acc = 0.f;
#pragma unroll
            for (int i = 0; i < 4; i++) {
                float4 a = mp[lane * 4 + i], x = vp[lane * 4 + i];
                acc += a.x * x.x + a.y * x.y + a.z * x.z + a.w * x.w;
            }
#pragma unroll
            for (int off = 16; off; off >>= 1)
                acc += __shfl_xor_sync(0xffffffffu, acc, off);
            if (lane == 0) s->oplog[w] = tanhfast(acc * 0.2f);
        }
        __syncthreads();
        if (tid < 32) {
            warp_sample(s->oplog, &s->gop[t * OPSN], OPSN,
                        &s->opIdx, &s->opLp, &s->opEnt, tid);
            if (tid == 0) {
                s->lpSum  += s->nodeLp + s->opLp;
                s->entSum += s->nodeEnt + s->opEnt;
                s->sel = s->opIdx;
                if (b == 0) {
                    out[2 * t]     = (float)s->nodeIdx;
                    out[2 * t + 1] = (float)s->opIdx;
                }
            }
        }
        __syncthreads();   // (H)
    }

    if (b == 0 && tid == 0) { out[64] = s->entSum; out[65] = s->lpSum; }
}

extern "C" void kernel_launch(void* const* d_in, const int* in_sizes, int n_in,
                              void* d_out, int out_size) {
    (void)in_sizes; (void)n_in; (void)out_size;
    cudaFuncSetAttribute(controller_kernel,
                         cudaFuncAttributeMaxDynamicSharedMemorySize,
                         (int)sizeof(SM));
    controller_kernel<<<GRIDL, NT, sizeof(SM)>>>(
        (const float*)d_in[0],  // embedding
        (const float*)d_in[1],  // w_ih
        (const float*)d_in[2],  // w_hh
        (const float*)d_in[3],  // b_ih
        (const float*)d_in[4],  // b_hh
        (const float*)d_in[5],  // w_attn_1
        (const float*)d_in[6],  // w_attn_2
        (const float*)d_in[7],  // index_fc
        (const float*)d_in[8],  // op_fc
        (float*)d_out);
}

// round 15
// speedup vs baseline: 1.2256x; 1.2256x over previous
#include <cuda_runtime.h>
#include <cstdint>

// ============================================================================
// NAS LSTM controller, 32 sequential steps, single persistent kernel.
// 64 worker CTAs x 512 threads (148 launched; extras exit). Weights in SMEM.
// Cross-CTA comm: epoch-tagged u64 words (tag<<32 | float), relaxed gpu-scope,
// batched retry-sweep polls. Partials feeding each round are computed from
// LOCAL slices before publishing (keeps cross-CTA dependency depth minimal).
// Exact JAX threefry2x32 sampling replicated per CTA (deterministic).
// ============================================================================

#define GRID   64
#define GRIDL  148
#define NT     512
#define D      512
#define LP1    33
#define NSTEP  32
#define OPSN   16

typedef unsigned long long u64t;

// ------------------------------ global state -------------------------------
__device__ u64t gPubA[GRID * 512];   // [src][dim] attn partials
__device__ u64t gPubH1[GRID * 8];    // [src][j]   h1 slices
__device__ u64t gPubI[GRID * 8];     // init h0 slices
__device__ u64t gPubL[LP1 * GRID];   // [anchor][src] node-logit partials
__device__ u64t gPubO[GRID * 24];    // [src][0..7]=h2, [8..23]=op partials
__device__ unsigned gEpochBase;

// ------------------------------ shared layout ------------------------------
struct __align__(16) SM {
    float Whh[32 * 512];       // 64 KB
    float Wih[32 * 512];       // 64 KB
    float A1[8 * 512];         // own rows of w_attn_1
    float A2T[8 * 512];        // [j][k]: w2[k][own dim j]
    float hprev[512];
    float h1full[512];
    float lsum[LP1 * 64];      // node-logit partials gathered
    float opP[OPSN * 64];
    float attnP[8 * 64];       // [own dim p][src c]
    float embG[17 * 32];       // x-gates (incl bias) per embedding
    float anchG[LP1 * 32];     // x-gates per anchor
    float anchW1[LP1 * 8];     // own slice of anchors_w1
    float OPFT[OPSN * 8];
    float gnode[NSTEP * LP1];
    float gop[NSTEP * OPSN];
    float vals[40];
    float hw2s[8];
    float idxfc8[8];
    float bias[32];
    float gbuf[32];
    float cslice[8];
    float h2own[8];
    float oplog[16];
    unsigned keys2[NSTEP * 2];
    int nodeIdx, opIdx, sel;
    float nodeLp, nodeEnt, opLp, opEnt, lpSum, entSum;
    unsigned base;
};

// --------------------------- tagged publish/poll ---------------------------
__device__ __forceinline__ void pub64(u64t* p, float v, unsigned tag) {
    u64t w = ((u64t)tag << 32) | (u64t)__float_as_uint(v);
    asm volatile("st.relaxed.gpu.global.u64 [%0], %1;" :: "l"(p), "l"(w) : "memory");
}
__device__ __forceinline__ u64t ldrx(const u64t* p) {
    u64t w;
    asm volatile("ld.relaxed.gpu.global.u64 %0, [%1];" : "=l"(w) : "l"(p) : "memory");
    return w;
}
__device__ __forceinline__ float lo32(u64t w) { return __uint_as_float((unsigned)w); }

// ------------------------------ threefry2x32 -------------------------------
__device__ __forceinline__ void tf2x32(unsigned k0, unsigned k1,
                                       unsigned x0, unsigned x1,
                                       unsigned& o0, unsigned& o1) {
    unsigned ks2 = k0 ^ k1 ^ 0x1BD11BDAu;
    x0 += k0; x1 += k1;
#define TFR(r) { x0 += x1; x1 = (x1 << (r)) | (x1 >> (32 - (r))); x1 ^= x0; }
    TFR(13) TFR(15) TFR(26) TFR(6)   x0 += k1;  x1 += ks2 + 1u;
    TFR(17) TFR(29) TFR(16) TFR(24)  x0 += ks2; x1 += k0 + 2u;
    TFR(13) TFR(15) TFR(26) TFR(6)   x0 += k0;  x1 += k1 + 3u;
    TFR(17) TFR(29) TFR(16) TFR(24)  x0 += k1;  x1 += ks2 + 4u;
    TFR(13) TFR(15) TFR(26) TFR(6)   x0 += ks2; x1 += k0 + 5u;
#undef TFR
    o0 = x0; o1 = x1;
}

__device__ __forceinline__ float gumbelf(unsigned bits) {
    float f = __uint_as_float((bits >> 9) | 0x3f800000u) - 1.0f;
    const float tiny = 1.17549435e-38f;
    float u = fmaxf(tiny, f * (1.0f - tiny) + tiny);
    return -logf(-logf(u));
}

__device__ __forceinline__ float sigf(float x) {
    return __fdividef(1.0f, 1.0f + __expf(-x));
}
__device__ __forceinline__ float tanhfast(float x) {
    return 1.0f - __fdividef(2.0f, __expf(2.0f * x) + 1.0f);
}

// LSTM cell: gates = Whh*hin + xc; update own c,h slice; tail (tid<8) writes
// houtOwn AND publishes the h slice immediately (early visibility), then the
// trailing block sync makes houtOwn readable by all threads.
__device__ __forceinline__ void cell_hh(SM* s, const float* hin, const float* xc,
                                        int tid, float* houtOwn,
                                        u64t* pubBase, unsigned tag) {
    int row = tid >> 4, lane = tid & 15;
    const float4* wp = (const float4*)&s->Whh[row * 512];
    const float4* vp = (const float4*)hin;
    float acc = 0.f;
#pragma unroll
    for (int i = 0; i < 8; i++) {
        float4 w = wp[i * 16 + lane], v = vp[i * 16 + lane];
        acc += w.x * v.x + w.y * v.y + w.z * v.z + w.w * v.w;
    }
#pragma unroll
    for (int o = 8; o; o >>= 1) acc += __shfl_down_sync(0xffffffffu, acc, o, 16);
    if (lane == 0) s->gbuf[row] = acc + xc[row];
    __syncthreads();
    if (tid < 8) {
        float gi = s->gbuf[tid],      gf = s->gbuf[8 + tid];
        float gg = s->gbuf[16 + tid], go = s->gbuf[24 + tid];
        float c2 = sigf(gf) * s->cslice[tid] + sigf(gi) * tanhfast(gg);
        float h2 = sigf(go) * tanhfast(c2);
        s->cslice[tid] = c2;
        houtOwn[tid] = h2;
        pub64(pubBase + tid, h2, tag);      // early publish
    }
    __syncthreads();
}

// 8 dots of an 8x512 smem matrix with v (threads 0..127), conflict-free.
__device__ __forceinline__ void attn_dot(const float* M, const float* v,
                                         float* dst, int tid) {
    if (tid < 128) {
        int r = tid >> 4, lane = tid & 15;
        const float4* mp = (const float4*)&M[r * 512];
        const float4* vp = (const float4*)v;
        float acc = 0.f;
#pragma unroll
        for (int i = 0; i < 8; i++) {
            float4 w = mp[i * 16 + lane], x = vp[i * 16 + lane];
            acc += w.x * x.x + w.y * x.y + w.z * x.z + w.w * x.w;
        }
#pragma unroll
        for (int o = 8; o; o >>= 1) acc += __shfl_down_sync(0xffffffffu, acc, o, 16);
        if (lane == 0) dst[r] = acc;
    }
}

// ----- warp-parallel categorical sample + lp + entropy (tid<32 only) -------
__device__ __forceinline__ void warp_sample(const float* vals, const float* g, int n,
                                            int* oIdx, float* oLp, float* oEnt, int lane) {
    const float NINF = __int_as_float(0xff800000);
    float v1 = (lane < n) ? vals[lane] : NINF;
    float d1 = (lane < n) ? v1 + g[lane] : NINF;
    int   i1 = lane;
    float v2 = NINF;
    if (lane == 0 && n > 32) {
        v2 = vals[32];
        float d2 = v2 + g[32];
        if (d2 > d1) { d1 = d2; i1 = 32; }
    }
#pragma unroll
    for (int off = 16; off; off >>= 1) {
        float dv = __shfl_down_sync(0xffffffffu, d1, off);
        int   di = __shfl_down_sync(0xffffffffu, i1, off);
        if (dv > d1 || (dv == d1 && di < i1)) { d1 = dv; i1 = di; }
    }
    int best = __shfl_sync(0xffffffffu, i1, 0);
    float m1 = (lane < n) ? v1 : NINF;
    if (lane == 0 && n > 32) m1 = fmaxf(m1, v2);
#pragma unroll
    for (int off = 16; off; off >>= 1) m1 = fmaxf(m1, __shfl_xor_sync(0xffffffffu, m1, off));
    float se = (lane < n) ? __expf(v1 - m1) : 0.f;
    if (lane == 0 && n > 32) se += __expf(v2 - m1);
#pragma unroll
    for (int off = 16; off; off >>= 1) se += __shfl_xor_sync(0xffffffffu, se, off);
    float lse = __logf(se);
    float ent = 0.f;
    if (lane < n)            { float l = v1 - m1 - lse; ent -= l * __expf(l); }
    if (lane == 0 && n > 32) { float l = v2 - m1 - lse; ent -= l * __expf(l); }
#pragma unroll
    for (int off = 16; off; off >>= 1) ent += __shfl_xor_sync(0xffffffffu, ent, off);
    if (lane == 0) {
        *oIdx = best;
        *oLp  = -(vals[best] - m1 - lse);
        *oEnt = ent;
    }
}

__global__ void __launch_bounds__(NT, 1)
controller_kernel(const float* __restrict__ emb,   const float* __restrict__ w_ih,
                  const float* __restrict__ w_hh,  const float* __restrict__ b_ih,
                  const float* __restrict__ b_hh,  const float* __restrict__ w1,
                  const float* __restrict__ w2,    const float* __restrict__ idxfc,
                  const float* __restrict__ opfc,  float* __restrict__ out) {
    if (blockIdx.x >= GRID) return;
    extern __shared__ __align__(16) float smraw[];
    SM* s = (SM*)smraw;
    const int tid = threadIdx.x;
    const int b   = blockIdx.x;

    // ---------------- setup ----------------
    if (tid == 0) {
        s->base = *(volatile unsigned*)&gEpochBase;
        s->sel = OPSN;
        s->lpSum = 0.f; s->entSum = 0.f;
    }
    for (int i = tid; i < 32 * 512; i += NT) {
        int row = i >> 9, k = i & 511;
        int gate = row >> 3, jj = row & 7;
        int grow = gate * 512 + b * 8 + jj;
        s->Whh[i] = w_hh[grow * 512 + k];
        s->Wih[i] = w_ih[grow * 512 + k];
    }
    for (int i = tid; i < 8 * 512; i += NT) {
        int a = i >> 9, k = i & 511;
        s->A1[i]  = w1[(b * 8 + a) * 512 + k];
        s->A2T[i] = w2[k * 512 + b * 8 + a];
    }
    if (tid < OPSN * 8) {
        int o = tid >> 3, j = tid & 7;
        s->OPFT[tid] = opfc[o * 512 + b * 8 + j];
    }
    if (tid < 32) {
        int gate = tid >> 3, jj = tid & 7;
        int grow = gate * 512 + b * 8 + jj;
        float bb = b_ih[grow] + b_hh[grow];
        s->bias[tid]  = bb;
        s->anchG[tid] = bb;      // anchor 0 = zeros -> x-gates = bias
    }
    if (tid < 8) { s->idxfc8[tid] = idxfc[b * 8 + tid]; s->cslice[tid] = 0.f; }
    if (tid < LP1 * 8) s->anchW1[tid] = 0.f;
    __syncthreads();

    // embGates for all 17 embeddings
    {
        int row = tid >> 4, lane = tid & 15;
        const float4* wr = (const float4*)&s->Wih[row * 512];
        for (int e = 0; e < 17; e++) {
            const float4* er = (const float4*)&emb[e * 512];
            float acc = 0.f;
#pragma unroll
            for (int i = 0; i < 8; i++) {
                float4 w = wr[i * 16 + lane];
                float4 v = __ldg(&er[i * 16 + lane]);
                acc += w.x * v.x + w.y * v.y + w.z * v.z + w.w * v.w;
            }
#pragma unroll
            for (int o = 8; o; o >>= 1) acc += __shfl_down_sync(0xffffffffu, acc, o, 16);
            if (lane == 0) s->embG[e * 32 + row] = acc + s->bias[row];
        }
    }
    // key chain (data-independent)
    if (tid == 0) {
        unsigned k0 = 0u, k1 = 42u;
        for (int t = 0; t < NSTEP; t++) {
            s->keys2[2 * t] = k0; s->keys2[2 * t + 1] = k1;
            unsigned o0, o1; tf2x32(k0, k1, 0u, 2u, o0, o1);
            k0 = o0; k1 = o1;
        }
    }
    __syncthreads();
    for (int p = tid; p < NSTEP * (LP1 + OPSN); p += NT) {
        int t = p / (LP1 + OPSN), r = p % (LP1 + OPSN);
        unsigned K0 = s->keys2[2 * t], K1 = s->keys2[2 * t + 1];
        unsigned c0, c1, o0, o1;
        if (r < LP1) {
            tf2x32(K0, K1, 0u, 0u, c0, c1);
            tf2x32(c0, c1, 0u, (unsigned)r, o0, o1);
            s->gnode[t * LP1 + r] = gumbelf(o0 ^ o1);
        } else {
            int o = r - LP1;
            tf2x32(K0, K1, 0u, 1u, c0, c1);
            tf2x32(c0, c1, 0u, (unsigned)o, o0, o1);
            s->gop[t * OPSN + o] = gumbelf(o0 ^ o1);
        }
    }
    __syncthreads();
    const unsigned base = s->base;

    // ---------------- initial cell: h0 = cell(emb[16], 0, 0) ----------------
    if (tid < 8) {
        float gi = s->embG[16 * 32 + tid];
        float gg = s->embG[16 * 32 + 16 + tid], go = s->embG[16 * 32 + 24 + tid];
        float c2 = sigf(gi) * tanhfast(gg);
        float h2 = sigf(go) * tanhfast(c2);
        s->cslice[tid] = c2;
        pub64(&gPubI[b * 8 + tid], h2, base + 1);
    }
    {
        int c = tid >> 3, p = tid & 7;
        u64t w;
        do { w = ldrx(&gPubI[c * 8 + p]); } while ((unsigned)(w >> 32) != base + 1);
        s->hprev[c * 8 + p] = lo32(w);
    }
    __syncthreads();
    if (b == 0 && tid == 0) *(volatile unsigned*)&gEpochBase = base + 128;

    // ---------------- main loop ----------------
    for (int t = 0; t < NSTEP; t++) {
        const unsigned tag1 = base + 2 + 3 * t;
        const unsigned tag2 = tag1 + 1;
        const unsigned tag3 = tag1 + 2;

        // cell1: h1 = cell(emb[sel], hprev, c); tail publishes h1 slice early
        cell_hh(s, s->hprev, &s->embG[s->sel * 32], tid, &s->h1full[b * 8],
                &gPubH1[b * 8], tag1);

        // publish round1: attn partial for global dim `tid` (local h1 slice)
        {
            float pa = 0.f;
#pragma unroll
            for (int j = 0; j < 8; j++)
                pa += s->A2T[j * 512 + tid] * s->h1full[b * 8 + j];
            pub64(&gPubA[b * 512 + tid], pa, tag1);
        }

        // overlap comm latency: anchor-t x-gates + anchW1[t] from hprev
        if (t > 0) {
            int row = tid >> 4, lane = tid & 15;
            const float4* wp = (const float4*)&s->Wih[row * 512];
            const float4* vp = (const float4*)s->hprev;
            float acc = 0.f;
#pragma unroll
            for (int i = 0; i < 8; i++) {
                float4 w = wp[i * 16 + lane], v = vp[i * 16 + lane];
                acc += w.x * v.x + w.y * v.y + w.z * v.z + w.w * v.w;
            }
#pragma unroll
            for (int o = 8; o; o >>= 1) acc += __shfl_down_sync(0xffffffffu, acc, o, 16);
            if (lane == 0) s->anchG[t * 32 + row] = acc + s->bias[row];
        }
        attn_dot(s->A1, s->hprev, &s->anchW1[t * 8], tid);
        __syncthreads();   // (A) anchW1/anchG ready

        // consume round1: batched 2-poll per thread
        {
            int c = tid >> 3, p = tid & 7;
            const u64t* q0 = &gPubA[c * 512 + b * 8 + p];
            const u64t* q1 = &gPubH1[c * 8 + p];
            float v0 = 0.f, v1 = 0.f;
            unsigned got = 0;
            while (got != 3u) {
                u64t w;
                if (!(got & 1u)) { w = ldrx(q0); if ((unsigned)(w >> 32) == tag1) { v0 = lo32(w); got |= 1u; } }
                if (!(got & 2u)) { w = ldrx(q1); if ((unsigned)(w >> 32) == tag1) { v1 = lo32(w); got |= 2u; } }
            }
            s->attnP[p * 64 + c]  = v0;
            s->h1full[c * 8 + p]  = v1;
        }
        __syncthreads();   // (B)
        if (tid < 8) {
            const float4* ap = (const float4*)&s->attnP[tid * 64];
            float sacc = 0.f;
#pragma unroll
            for (int i = 0; i < 16; i++) { float4 v = ap[i]; sacc += v.x + v.y + v.z + v.w; }
            s->hw2s[tid] = sacc;
        }
        __syncthreads();   // (C)

        // node-logit partial: shuffle-reduce in 8-lane groups, publish directly
        if (tid < 288) {
            int a = tid >> 3; if (a > 32) a = 32;
            int rl = tid & 7;
            float q = tanhfast(s->anchW1[a * 8 + rl] + s->hw2s[rl]) * s->idxfc8[rl];
#pragma unroll
            for (int o = 4; o; o >>= 1) q += __shfl_down_sync(0xffffffffu, q, o, 8);
            if (rl == 0 && tid < 264 && a <= t) pub64(&gPubL[a * 64 + b], q, tag2);
        }

        // consume round2: (t+1)*64 words, batched <=4 polls/thread
        {
            int cnt = (t + 1) * 64;
            int k0 = tid, k1 = tid + 512, k2 = tid + 1024, k3 = tid + 1536;
            unsigned need = (k0 < cnt ? 1u : 0u) | (k1 < cnt ? 2u : 0u) |
                            (k2 < cnt ? 4u : 0u) | (k3 < cnt ? 8u : 0u);
            unsigned got = 0;
            float v0 = 0.f, v1 = 0.f, v2 = 0.f, v3 = 0.f;
            while (got != need) {
                u64t w;
                if ((need & 1u) && !(got & 1u)) { w = ldrx(&gPubL[k0]); if ((unsigned)(w >> 32) == tag2) { v0 = lo32(w); got |= 1u; } }
                if ((need & 2u) && !(got & 2u)) { w = ldrx(&gPubL[k1]); if ((unsigned)(w >> 32) == tag2) { v1 = lo32(w); got |= 2u; } }
                if ((need & 4u) && !(got & 4u)) { w = ldrx(&gPubL[k2]); if ((unsigned)(w >> 32) == tag2) { v2 = lo32(w); got |= 4u; } }
                if ((need & 8u) && !(got & 8u)) { w = ldrx(&gPubL[k3]); if ((unsigned)(w >> 32) == tag2) { v3 = lo32(w); got |= 8u; } }
            }
            if (need & 1u) s->lsum[k0] = v0;
            if (need & 2u) s->lsum[k1] = v1;
            if (need & 4u) s->lsum[k2] = v2;
            if (need & 8u) s->lsum[k3] = v3;
        }
        __syncthreads();   // (D)
        if (tid < LP1) {
            float v;
            if (tid <= t) {
                const float4* lp = (const float4*)&s->lsum[tid * 64];
                v = 0.f;
#pragma unroll
                for (int i = 0; i < 16; i++) { float4 x = lp[i]; v += x.x + x.y + x.z + x.w; }
                v = 2.5f * tanhfast(v * 0.2f);
            } else v = -1e9f;
            s->vals[tid] = v;
        }
        __syncthreads();   // (E)
        if (tid < 32)
            warp_sample(s->vals, &s->gnode[t * LP1], LP1,
                        &s->nodeIdx, &s->nodeLp, &s->nodeEnt, tid);
        __syncthreads();   // (F)

        // cell2: h2 = cell(anchor[nodeIdx], h1, c); tail publishes h2 early
        cell_hh(s, s->h1full, &s->anchG[s->nodeIdx * 32], tid, s->h2own,
                &gPubO[b * 24], tag3);

        // publish round3 remainder: op partials from local h2 slice
        if (tid >= 8 && tid < 24) {
            int o = tid - 8;
            float oa = 0.f;
#pragma unroll
            for (int j = 0; j < 8; j++) oa += s->OPFT[o * 8 + j] * s->h2own[j];
            pub64(&gPubO[b * 24 + 8 + o], oa, tag3);
        }

        // consume round3: 1536 words, batched 3 polls per thread
        {
            int k0 = tid, k1 = tid + 512, k2 = tid + 1024;
            unsigned got = 0;
            float v0 = 0.f, v1 = 0.f, v2 = 0.f;
            while (got != 7u) {
                u64t w;
                if (!(got & 1u)) { w = ldrx(&gPubO[k0]); if ((unsigned)(w >> 32) == tag3) { v0 = lo32(w); got |= 1u; } }
                if (!(got & 2u)) { w = ldrx(&gPubO[k1]); if ((unsigned)(w >> 32) == tag3) { v1 = lo32(w); got |= 2u; } }
                if (!(got & 4u)) { w = ldrx(&gPubO[k2]); if ((unsigned)(w >> 32) == tag3) { v2 = lo32(w); got |= 4u; } }
            }
            int c0 = k0 / 24, i0 = k0 - c0 * 24;
            int c1 = k1 / 24, i1 = k1 - c1 * 24;
            int c2 = k2 / 24, i2 = k2 - c2 * 24;
            if (i0 < 8) s->hprev[c0 * 8 + i0] = v0; else s->opP[(i0 - 8) * 64 + c0] = v0;
            if (i1 < 8) s->hprev[c1 * 8 + i1] = v1; else s->opP[(i1 - 8) * 64 + c1] = v1;
            if (i2 < 8) s->hprev[c2 * 8 + i2] = v2; else s->opP[(i2 - 8) * 64 + c2] = v2;
        }
        __syncthreads();   // (G)

        // warp0: op logits + sample + bookkeeping
        if (tid < 32) {
            if (tid < 16) {
                const float4* op = (const float4*)&s->opP[tid * 64];
                float osum = 0.f;
#pragma unroll
                for (int i = 0; i < 16; i++) { float4 v = op[i]; osum += v.x + v.y + v.z + v.w; }
                s->oplog[tid] = tanhfast(osum * 0.2f);
            }
            __syncwarp();
            warp_sample(s->oplog, &s->gop[t * OPSN], OPSN,
                        &s->opIdx, &s->opLp, &s->opEnt, tid);
            if (tid == 0) {
                s->lpSum  += s->nodeLp + s->opLp;
                s->entSum += s->nodeEnt + s->opEnt;
                s->sel = s->opIdx;
                if (b == 0) {
                    out[2 * t]     = (float)s->nodeIdx;
                    out[2 * t + 1] = (float)s->opIdx;
                }
            }
        }
        __syncthreads();   // (H)
    }

    if (b == 0 && tid == 0) { out[64] = s->entSum; out[65] = s->lpSum; }
}

extern "C" void kernel_launch(void* const* d_in, const int* in_sizes, int n_in,
                              void* d_out, int out_size) {
    (void)in_sizes; (void)n_in; (void)out_size;
    cudaFuncSetAttribute(controller_kernel,
                         cudaFuncAttributeMaxDynamicSharedMemorySize,
                         (int)sizeof(SM));
    controller_kernel<<<GRIDL, NT, sizeof(SM)>>>(
        (const float*)d_in[0],  // embedding
        (const float*)d_in[1],  // w_ih
        (const float*)d_in[2],  // w_hh
        (const float*)d_in[3],  // b_ih
        (const float*)d_in[4],  // b_hh
        (const float*)d_in[5],  // w_attn_1
        (const float*)d_in[6],  // w_attn_2
        (const float*)d_in[7],  // index_fc
        (const float*)d_in[8],  // op_fc
        (float*)d_out);
}